// round 2
// baseline (speedup 1.0000x reference)
#include <cuda_runtime.h>
#include <cstdint>

// ============================================================================
// Problem constants
// ============================================================================
#define M_TOK   8192        // B*S tokens
#define K_DIM   4096        // IN
#define N_DIM   4096        // OUT

#define BM 128
#define BN 128
#define BK 64
#define NK (K_DIM / BK)     // 64 k-tiles
#define STAGES 4
#define THREADS 256

#define A_TILE_BYTES (BM * BK)          // 8192
#define B_TILE_BYTES (BN * BK)          // 8192
#define STAGE_BYTES  (A_TILE_BYTES + B_TILE_BYTES)   // 16384
#define SMEM_TOTAL   (STAGES * STAGE_BYTES)          // 65536

// ============================================================================
// Device scratch (no dynamic allocation allowed)
// ============================================================================
__device__ __align__(1024) int8_t g_xq[(size_t)M_TOK * K_DIM];   // 32 MB
__device__ __align__(1024) int8_t g_wb[(size_t)N_DIM * K_DIM];   // 16 MB
__device__ float g_alpha[M_TOK];

// ============================================================================
// PTX helpers
// ============================================================================
__device__ __forceinline__ uint32_t smem_to_u32(const void* p) {
    uint32_t a;
    asm("{ .reg .u64 t; cvta.to.shared.u64 t, %1; cvt.u32.u64 %0, t; }"
        : "=r"(a) : "l"(p));
    return a;
}

__device__ __forceinline__ void cp_async16(uint32_t smem_addr, const void* gptr) {
    asm volatile("cp.async.cg.shared.global [%0], [%1], 16;"
                 :: "r"(smem_addr), "l"(gptr) : "memory");
}
__device__ __forceinline__ void cp_commit() {
    asm volatile("cp.async.commit_group;" ::: "memory");
}
template <int N>
__device__ __forceinline__ void cp_wait() {
    asm volatile("cp.async.wait_group %0;" :: "n"(N) : "memory");
}

__device__ __forceinline__ void mma_s8(int* c, uint32_t a0, uint32_t a1,
                                       uint32_t a2, uint32_t a3,
                                       uint32_t b0, uint32_t b1) {
    asm volatile(
        "mma.sync.aligned.m16n8k32.row.col.s32.s8.s8.s32 "
        "{%0,%1,%2,%3}, {%4,%5,%6,%7}, {%8,%9}, {%0,%1,%2,%3};"
        : "+r"(c[0]), "+r"(c[1]), "+r"(c[2]), "+r"(c[3])
        : "r"(a0), "r"(a1), "r"(a2), "r"(a3), "r"(b0), "r"(b1));
}

// ============================================================================
// Kernel 1: per-token absmax quantize x -> int8, alpha = gamma/127*scale
// ============================================================================
__global__ void __launch_bounds__(128)
quant_kernel(const float* __restrict__ x, const float* __restrict__ scale_p,
             int8_t* __restrict__ xq, float* __restrict__ alpha)
{
    const int token = blockIdx.x;
    const int tid = threadIdx.x;
    const float4* xr = reinterpret_cast<const float4*>(x + (size_t)token * K_DIM);

    float4 v[8];
    float m = 0.0f;
#pragma unroll
    for (int i = 0; i < 8; i++) {
        v[i] = xr[tid + i * 128];
        m = fmaxf(m, fmaxf(fmaxf(fabsf(v[i].x), fabsf(v[i].y)),
                           fmaxf(fabsf(v[i].z), fabsf(v[i].w))));
    }
#pragma unroll
    for (int o = 16; o; o >>= 1) m = fmaxf(m, __shfl_xor_sync(0xFFFFFFFFu, m, o));

    __shared__ float wmax[4];
    __shared__ float s_inv;
    if ((tid & 31) == 0) wmax[tid >> 5] = m;
    __syncthreads();
    if (tid == 0) {
        float g = fmaxf(fmaxf(wmax[0], wmax[1]), fmaxf(wmax[2], wmax[3]));
        g = fmaxf(g, 1e-5f);
        s_inv = 127.0f / g;
        alpha[token] = g * (1.0f / 127.0f) * scale_p[0];
    }
    __syncthreads();
    const float inv = s_inv;

    int* xqr = reinterpret_cast<int*>(xq + (size_t)token * K_DIM);
#pragma unroll
    for (int i = 0; i < 8; i++) {
        int q0 = (int)fminf(fmaxf(rintf(v[i].x * inv), -127.0f), 127.0f);
        int q1 = (int)fminf(fmaxf(rintf(v[i].y * inv), -127.0f), 127.0f);
        int q2 = (int)fminf(fmaxf(rintf(v[i].z * inv), -127.0f), 127.0f);
        int q3 = (int)fminf(fmaxf(rintf(v[i].w * inv), -127.0f), 127.0f);
        int packed = (q0 & 0xFF) | ((q1 & 0xFF) << 8) |
                     ((q2 & 0xFF) << 16) | (q3 << 24);
        xqr[tid + i * 128] = packed;
    }
}

// ============================================================================
// Kernel 2: w (float, values in {-1,0,1}) -> int8
// ============================================================================
__global__ void __launch_bounds__(256)
wconv_kernel(const float* __restrict__ w, int8_t* __restrict__ wb)
{
    size_t idx = (size_t)blockIdx.x * blockDim.x + threadIdx.x;  // float4 index
    float4 v = reinterpret_cast<const float4*>(w)[idx];
    int q0 = (int)v.x, q1 = (int)v.y, q2 = (int)v.z, q3 = (int)v.w;
    int packed = (q0 & 0xFF) | ((q1 & 0xFF) << 8) |
                 ((q2 & 0xFF) << 16) | (q3 << 24);
    reinterpret_cast<int*>(wb)[idx] = packed;
}

// ============================================================================
// Kernel 3: int8 IMMA GEMM, BM=128 x BN=128 x BK=64, 4-stage cp.async pipeline
// y[m,n] = sum_k xq[m,k] * wb[n,k];  out = float(y) * alpha[m]
//
// 8 warps: warp grid 4 (M) x 2 (N); warp tile 32 (M) x 64 (N).
// SMEM swizzle: byte offset o within a tile -> o ^ ((o>>3)&0x30)
// (XOR row bits 1,2 into k-offset bits 4,5).  For rows of 64 B this makes
// all fragment LDS.32 accesses bank-conflict-free.
// ============================================================================
__global__ void __launch_bounds__(THREADS)
bitlinear_gemm(const int8_t* __restrict__ xq, const int8_t* __restrict__ wb,
               const float* __restrict__ alpha, float* __restrict__ out)
{
    extern __shared__ int8_t smem[];
    const uint32_t smem_u = smem_to_u32(smem);

    const int tid  = threadIdx.x;
    const int lane = tid & 31;
    const int wid  = tid >> 5;
    const int wm   = wid >> 1;            // 0..3 (M dim)
    const int wn   = wid & 1;             // 0..1 (N dim)

    const int m0 = blockIdx.y * BM;
    const int n0 = blockIdx.x * BN;

    // --- cp.async source/dest precompute (2 A chunks + 2 B chunks / thread) ---
    // linear = tid + i*256; row = linear>>2 (0..127), c16 = linear&3 (16B col)
    int ld_row[2], ld_dst[2];
#pragma unroll
    for (int i = 0; i < 2; i++) {
        int lin = tid + i * THREADS;
        int row = lin >> 2;
        int c16 = lin & 3;
        ld_row[i] = row;
        ld_dst[i] = row * 64 + ((c16 * 16) ^ ((row & 6) << 3));
    }

    // --- fragment LDS offsets ---
    const int kx = ((lane >> 2) & 6) << 3;     // swizzle mask (thread-constant)
    const int kq = (lane & 3) * 4;
    // koff[s][t]: k-byte offset for kstep s (0/1), half t (0/1 = k, k+16)
    int koff[2][2];
#pragma unroll
    for (int s = 0; s < 2; s++)
#pragma unroll
        for (int t = 0; t < 2; t++)
            koff[s][t] = (s * 32 + kq + t * 16) ^ kx;

    const int arow_base = (wm * 32 + (lane >> 2)) * 64;   // bytes into A tile
    const int brow_base = (wn * 64 + (lane >> 2)) * 64;   // bytes into B tile

    int acc[2][8][4];
#pragma unroll
    for (int f = 0; f < 2; f++)
#pragma unroll
        for (int j = 0; j < 8; j++)
#pragma unroll
            for (int c = 0; c < 4; c++) acc[f][j][c] = 0;

    const int8_t* gA = xq + (size_t)m0 * K_DIM;
    const int8_t* gB = wb + (size_t)n0 * K_DIM;

    // --- prologue: issue STAGES-1 stages ---
#pragma unroll
    for (int s = 0; s < STAGES - 1; s++) {
#pragma unroll
        for (int i = 0; i < 2; i++) {
            int lin = tid + i * THREADS;
            int c16 = lin & 3;
            cp_async16(smem_u + s * STAGE_BYTES + ld_dst[i],
                       gA + (size_t)ld_row[i] * K_DIM + s * BK + c16 * 16);
            cp_async16(smem_u + s * STAGE_BYTES + A_TILE_BYTES + ld_dst[i],
                       gB + (size_t)ld_row[i] * K_DIM + s * BK + c16 * 16);
        }
        cp_commit();
    }

    // --- mainloop ---
    for (int kt = 0; kt < NK; kt++) {
        cp_wait<STAGES - 2>();
        __syncthreads();

        // issue stage kt+STAGES-1 into buffer (kt-1)%STAGES (safe after sync)
        int jt = kt + STAGES - 1;
        if (jt < NK) {
            int sb = jt & (STAGES - 1);
#pragma unroll
            for (int i = 0; i < 2; i++) {
                int lin = tid + i * THREADS;
                int c16 = lin & 3;
                cp_async16(smem_u + sb * STAGE_BYTES + ld_dst[i],
                           gA + (size_t)ld_row[i] * K_DIM + jt * BK + c16 * 16);
                cp_async16(smem_u + sb * STAGE_BYTES + A_TILE_BYTES + ld_dst[i],
                           gB + (size_t)ld_row[i] * K_DIM + jt * BK + c16 * 16);
            }
        }
        cp_commit();

        // compute on stage kt % STAGES
        const int8_t* aT = smem + (kt & (STAGES - 1)) * STAGE_BYTES;
        const int8_t* bT = aT + A_TILE_BYTES;

#pragma unroll
        for (int s = 0; s < 2; s++) {
            uint32_t af[2][4];
#pragma unroll
            for (int f = 0; f < 2; f++) {
                int rb = arow_base + f * 1024;
                af[f][0] = *(const uint32_t*)(aT + rb +       koff[s][0]);
                af[f][1] = *(const uint32_t*)(aT + rb + 512 + koff[s][0]);
                af[f][2] = *(const uint32_t*)(aT + rb +       koff[s][1]);
                af[f][3] = *(const uint32_t*)(aT + rb + 512 + koff[s][1]);
            }
#pragma unroll
            for (int j = 0; j < 8; j++) {
                uint32_t b0 = *(const uint32_t*)(bT + brow_base + j * 512 + koff[s][0]);
                uint32_t b1 = *(const uint32_t*)(bT + brow_base + j * 512 + koff[s][1]);
                mma_s8(acc[0][j], af[0][0], af[0][1], af[0][2], af[0][3], b0, b1);
                mma_s8(acc[1][j], af[1][0], af[1][1], af[1][2], af[1][3], b0, b1);
            }
        }
    }

    // --- epilogue: dequantize + store ---
#pragma unroll
    for (int f = 0; f < 2; f++) {
        int r0 = m0 + wm * 32 + f * 16 + (lane >> 2);
        float al0 = alpha[r0];
        float al1 = alpha[r0 + 8];
        float* o0 = out + (size_t)r0 * N_DIM + n0 + wn * 64 + (lane & 3) * 2;
        float* o1 = o0 + (size_t)8 * N_DIM;
#pragma unroll
        for (int j = 0; j < 8; j++) {
            float2 v0, v1;
            v0.x = (float)acc[f][j][0] * al0;
            v0.y = (float)acc[f][j][1] * al0;
            v1.x = (float)acc[f][j][2] * al1;
            v1.y = (float)acc[f][j][3] * al1;
            *reinterpret_cast<float2*>(o0 + j * 8) = v0;
            *reinterpret_cast<float2*>(o1 + j * 8) = v1;
        }
    }
}

// ============================================================================
// Host side
// ============================================================================
extern "C" void kernel_launch(void* const* d_in, const int* in_sizes, int n_in,
                              void* d_out, int out_size)
{
    const float* x     = (const float*)d_in[0];
    const float* w     = (const float*)d_in[1];
    const float* scale = (const float*)d_in[2];
    float* out = (float*)d_out;

    void *xq_p = nullptr, *wb_p = nullptr, *al_p = nullptr;
    cudaGetSymbolAddress(&xq_p, g_xq);
    cudaGetSymbolAddress(&wb_p, g_wb);
    cudaGetSymbolAddress(&al_p, g_alpha);

    // Phase 1: quantize activations + convert weights
    quant_kernel<<<M_TOK, 128>>>(x, scale, (int8_t*)xq_p, (float*)al_p);
    wconv_kernel<<<((size_t)N_DIM * K_DIM) / (256 * 4), 256>>>(w, (int8_t*)wb_p);

    // Phase 2: GEMM
    static bool attr_set = false;
    if (!attr_set) {
        cudaFuncSetAttribute(bitlinear_gemm,
                             cudaFuncAttributeMaxDynamicSharedMemorySize,
                             SMEM_TOTAL);
        attr_set = true;
    }
    dim3 grid(N_DIM / BN, M_TOK / BM);   // 32 x 64 = 2048 CTAs
    bitlinear_gemm<<<grid, THREADS, SMEM_TOTAL>>>(
        (const int8_t*)xq_p, (const int8_t*)wb_p, (const float*)al_p, out);
}